// round 1
// baseline (speedup 1.0000x reference)
#include <cuda_runtime.h>
#include <math.h>

#define DEV_INLINE __device__ __forceinline__

// Problem constants (shapes fixed by the dataset; N/NNZ/B read from in_sizes)
static const int D   = 128;
static const int LSEQ = 256;
static const int HEADS = 8;
static const int DK  = 16;
static const int DI  = 512;

// ------------------------- scratch (device globals) -------------------------
__device__ float g_side[12800000];   // side = A_in @ ego   (N x 128)
__device__ float g_q [1048576];
__device__ float g_k [1048576];
__device__ float g_v [1048576];
__device__ float g_o [1048576];
__device__ float g_t [1048576];
__device__ float g_x1[1048576];
__device__ float g_x2[1048576];
__device__ float g_h [4194304];      // 8192 x 512

enum { BQ = 0, BK = 1, BV = 2, BO = 3, BT = 4, BX1 = 5, BX2 = 6, BH = 7 };

DEV_INLINE float* bufptr(int id) {
    switch (id) {
        case BQ:  return g_q;
        case BK:  return g_k;
        case BV:  return g_v;
        case BO:  return g_o;
        case BT:  return g_t;
        case BX1: return g_x1;
        case BX2: return g_x2;
        case BH:  return g_h;
    }
    return nullptr;
}

// ------------------------------ zero side ------------------------------
__global__ void zero_side_kernel(int n4) {
    float4* p = reinterpret_cast<float4*>(g_side);
    int i = blockIdx.x * blockDim.x + threadIdx.x;
    int stride = gridDim.x * blockDim.x;
    float4 z = make_float4(0.f, 0.f, 0.f, 0.f);
    for (; i < n4; i += stride) p[i] = z;
}

// ------------------------------ SpMM (COO, rows sorted) ------------------------------
// One warp handles EPW consecutive nnz. Lane j owns 4 dims (float4 of the 128-dim row).
// Accumulate while row id unchanged; flush with atomics on change (rows are sorted, so
// flushes ~= distinct-row-runs ~= N + #chunks).
static const int EPW = 256;

DEV_INLINE void spmm_flush(int row, int lane, float4 acc) {
    float* p = &g_side[(size_t)row * 128 + lane * 4];
    atomicAdd(p + 0, acc.x);
    atomicAdd(p + 1, acc.y);
    atomicAdd(p + 2, acc.z);
    atomicAdd(p + 3, acc.w);
}

__global__ void __launch_bounds__(256) spmm_kernel(
    const float* __restrict__ ego, const float* __restrict__ vals,
    const int* __restrict__ rows, const int* __restrict__ cols, int nnz)
{
    int warp = (blockIdx.x * blockDim.x + threadIdx.x) >> 5;
    int lane = threadIdx.x & 31;
    long e0 = (long)warp * EPW;
    if (e0 >= nnz) return;
    long e1 = e0 + EPW; if (e1 > nnz) e1 = nnz;

    const float4* ego4 = reinterpret_cast<const float4*>(ego);
    float4 acc = make_float4(0.f, 0.f, 0.f, 0.f);
    int cur = rows[e0];
    for (long e = e0; e < e1; e++) {
        int r = rows[e];
        if (r != cur) {
            spmm_flush(cur, lane, acc);
            acc = make_float4(0.f, 0.f, 0.f, 0.f);
            cur = r;
        }
        float v  = vals[e];
        float4 g = ego4[(size_t)cols[e] * 32 + lane];
        acc.x += v * g.x; acc.y += v * g.y; acc.z += v * g.z; acc.w += v * g.w;
    }
    spmm_flush(cur, lane, acc);
}

// ------------------------------ aggregator ------------------------------
// agg = leaky_relu((ego+side)@W1 + b1) + leaky_relu((ego*side)@W2 + b2)
// Block: 128 threads, 8 rows. Thread = output column.
__global__ void __launch_bounds__(128) agg_kernel(
    const float* __restrict__ ego,
    const float* __restrict__ W1, const float* __restrict__ b1,
    const float* __restrict__ W2, const float* __restrict__ b2,
    float* __restrict__ out, int M)
{
    __shared__ __align__(16) float s[8][128];
    __shared__ __align__(16) float p[8][128];
    int tid = threadIdx.x;
    int row0 = blockIdx.x * 8;

    #pragma unroll
    for (int r = 0; r < 8; r++) {
        int rr = row0 + r;
        float e = 0.f, sd = 0.f;
        if (rr < M) {
            e  = ego   [(size_t)rr * 128 + tid];
            sd = g_side[(size_t)rr * 128 + tid];
        }
        s[r][tid] = e + sd;
        p[r][tid] = e * sd;
    }
    __syncthreads();

    float a1[8], a2[8];
    float bb1 = b1[tid], bb2 = b2[tid];
    #pragma unroll
    for (int r = 0; r < 8; r++) { a1[r] = bb1; a2[r] = bb2; }

    for (int k4 = 0; k4 < 32; k4++) {
        float w1[4], w2[4];
        #pragma unroll
        for (int kk = 0; kk < 4; kk++) {
            w1[kk] = W1[(k4 * 4 + kk) * 128 + tid];
            w2[kk] = W2[(k4 * 4 + kk) * 128 + tid];
        }
        #pragma unroll
        for (int r = 0; r < 8; r++) {
            float4 sv = *reinterpret_cast<const float4*>(&s[r][k4 * 4]);
            float4 pv = *reinterpret_cast<const float4*>(&p[r][k4 * 4]);
            a1[r] += sv.x * w1[0] + sv.y * w1[1] + sv.z * w1[2] + sv.w * w1[3];
            a2[r] += pv.x * w2[0] + pv.y * w2[1] + pv.z * w2[2] + pv.w * w2[3];
        }
    }

    #pragma unroll
    for (int r = 0; r < 8; r++) {
        int rr = row0 + r;
        if (rr < M) {
            float v1 = a1[r]; v1 = (v1 > 0.f) ? v1 : 0.01f * v1;
            float v2 = a2[r]; v2 = (v2 > 0.f) ? v2 : 0.01f * v2;
            out[(size_t)rr * 128 + tid] = v1 + v2;
        }
    }
}

// ------------------------------ generic GEMM ------------------------------
// C[M,N] = A[M,K] @ W[K,N] + bias; mode 0: store, 1: relu, 2: + residual.
// Block: 128 threads, 8 rows, CPT = N/128 cols per thread.
template <int K, int N>
__global__ void __launch_bounds__(128) gemm_kernel(
    const float* __restrict__ Aext, int Aid,
    const float* __restrict__ W, const float* __restrict__ bias,
    const float* __restrict__ Rext, int Rid,
    float* __restrict__ Cext, int Cid, int M, int mode)
{
    constexpr int ROWS = 8;
    constexpr int CPT  = N / 128;
    const float* A = Aext ? Aext : bufptr(Aid);
    float*       C = Cext ? Cext : bufptr(Cid);
    const float* R = nullptr;
    if (mode == 2) R = Rext ? Rext : bufptr(Rid);

    __shared__ __align__(16) float As[ROWS][K];
    int tid  = threadIdx.x;
    int row0 = blockIdx.x * ROWS;

    const float4* A4  = reinterpret_cast<const float4*>(A);
    float4*       As4 = reinterpret_cast<float4*>(&As[0][0]);
    constexpr int K4 = K / 4;
    for (int idx = tid; idx < ROWS * K4; idx += 128) {
        int r = idx / K4, c = idx - r * K4;
        int rr = row0 + r;
        As4[idx] = (rr < M) ? A4[(size_t)rr * K4 + c] : make_float4(0.f, 0.f, 0.f, 0.f);
    }
    __syncthreads();

    float acc[ROWS][CPT];
    #pragma unroll
    for (int c = 0; c < CPT; c++) {
        float b = bias[tid + c * 128];
        #pragma unroll
        for (int r = 0; r < ROWS; r++) acc[r][c] = b;
    }

    for (int k4 = 0; k4 < K4; k4++) {
        float w[4][CPT];
        #pragma unroll
        for (int kk = 0; kk < 4; kk++)
            #pragma unroll
            for (int c = 0; c < CPT; c++)
                w[kk][c] = W[(k4 * 4 + kk) * N + tid + c * 128];
        #pragma unroll
        for (int r = 0; r < ROWS; r++) {
            float4 a = *reinterpret_cast<const float4*>(&As[r][k4 * 4]);
            #pragma unroll
            for (int c = 0; c < CPT; c++)
                acc[r][c] += a.x * w[0][c] + a.y * w[1][c] + a.z * w[2][c] + a.w * w[3][c];
        }
    }

    #pragma unroll
    for (int r = 0; r < ROWS; r++) {
        int rr = row0 + r;
        if (rr >= M) continue;
        #pragma unroll
        for (int c = 0; c < CPT; c++) {
            float v = acc[r][c];
            if (mode == 1) v = fmaxf(v, 0.f);
            else if (mode == 2) v += R[(size_t)rr * N + tid + c * 128];
            C[(size_t)rr * N + tid + c * 128] = v;
        }
    }
}

// ------------------------------ attention ------------------------------
// Block per (b, h): K_h and V_h tiles (256x16 each) in smem; thread = query row l.
// Online softmax (Dk=16 accumulator in registers).
__global__ void __launch_bounds__(256) attn_kernel(int unused)
{
    __shared__ __align__(16) float Ks[LSEQ * DK];
    __shared__ __align__(16) float Vs[LSEQ * DK];
    int b = blockIdx.x >> 3;
    int h = blockIdx.x & 7;
    int tid = threadIdx.x;           // 0..255 = query index l
    int base = (b * LSEQ) * D + h * DK;

    for (int idx = tid; idx < LSEQ * DK; idx += 256) {
        int m = idx >> 4, j = idx & 15;
        Ks[idx] = g_k[base + m * D + j];
        Vs[idx] = g_v[base + m * D + j];
    }
    __syncthreads();

    float q[16];
    {
        const float4* qp = reinterpret_cast<const float4*>(g_q + base + tid * D);
        #pragma unroll
        for (int jj = 0; jj < 4; jj++) {
            float4 t = qp[jj];
            q[jj * 4 + 0] = t.x; q[jj * 4 + 1] = t.y; q[jj * 4 + 2] = t.z; q[jj * 4 + 3] = t.w;
        }
    }

    float acc[16];
    #pragma unroll
    for (int j = 0; j < 16; j++) acc[j] = 0.f;
    float mx = -3.0e38f, sum = 0.f;

    const float4* Ks4 = reinterpret_cast<const float4*>(Ks);
    const float4* Vs4 = reinterpret_cast<const float4*>(Vs);

    for (int m = 0; m < LSEQ; m++) {
        float s = 0.f;
        #pragma unroll
        for (int jj = 0; jj < 4; jj++) {
            float4 kk = Ks4[m * 4 + jj];
            s += q[jj * 4 + 0] * kk.x + q[jj * 4 + 1] * kk.y
               + q[jj * 4 + 2] * kk.z + q[jj * 4 + 3] * kk.w;
        }
        s *= 0.25f;  // 1/sqrt(16)
        float mnew = fmaxf(mx, s);
        float corr = __expf(mx - mnew);
        float pe   = __expf(s - mnew);
        sum = sum * corr + pe;
        #pragma unroll
        for (int jj = 0; jj < 4; jj++) {
            float4 vv = Vs4[m * 4 + jj];
            acc[jj * 4 + 0] = acc[jj * 4 + 0] * corr + pe * vv.x;
            acc[jj * 4 + 1] = acc[jj * 4 + 1] * corr + pe * vv.y;
            acc[jj * 4 + 2] = acc[jj * 4 + 2] * corr + pe * vv.z;
            acc[jj * 4 + 3] = acc[jj * 4 + 3] * corr + pe * vv.w;
        }
        mx = mnew;
    }

    float inv = 1.f / sum;
    float* op = g_o + base + tid * D;
    #pragma unroll
    for (int j = 0; j < 16; j++) op[j] = acc[j] * inv;
}

// ------------------------------ LayerNorm (reads g_t) ------------------------------
__global__ void __launch_bounds__(128) ln_kernel(
    const float* __restrict__ gamma, const float* __restrict__ beta,
    float* __restrict__ outext, int outid)
{
    float* out = outext ? outext : bufptr(outid);
    int row = blockIdx.x, tid = threadIdx.x;
    float v = g_t[(size_t)row * 128 + tid];

    float s = v, sq = v * v;
    #pragma unroll
    for (int o = 16; o > 0; o >>= 1) {
        s  += __shfl_xor_sync(0xffffffff, s,  o);
        sq += __shfl_xor_sync(0xffffffff, sq, o);
    }
    __shared__ float rs[4], rq[4];
    int w = tid >> 5, lane = tid & 31;
    if (lane == 0) { rs[w] = s; rq[w] = sq; }
    __syncthreads();
    float S = rs[0] + rs[1] + rs[2] + rs[3];
    float Q = rq[0] + rq[1] + rq[2] + rq[3];
    float m   = S * (1.f / 128.f);
    float var = Q * (1.f / 128.f) - m * m;
    float r   = rsqrtf(var + 1e-5f);
    out[(size_t)row * 128 + tid] = (v - m) * r * gamma[tid] + beta[tid];
}

// ------------------------------ launch ------------------------------
extern "C" void kernel_launch(void* const* d_in, const int* in_sizes, int n_in,
                              void* d_out, int out_size)
{
    const float* ego    = (const float*)d_in[0];
    const float* vals   = (const float*)d_in[1];
    const float* W1     = (const float*)d_in[2];
    const float* b1     = (const float*)d_in[3];
    const float* W2     = (const float*)d_in[4];
    const float* b2     = (const float*)d_in[5];
    const float* enc_in = (const float*)d_in[6];
    const float* wq     = (const float*)d_in[7];
    const float* bq     = (const float*)d_in[8];
    const float* wk     = (const float*)d_in[9];
    const float* bk     = (const float*)d_in[10];
    const float* wv     = (const float*)d_in[11];
    const float* bv     = (const float*)d_in[12];
    const float* wo     = (const float*)d_in[13];
    const float* bo     = (const float*)d_in[14];
    const float* ln1_g  = (const float*)d_in[15];
    const float* ln1_b  = (const float*)d_in[16];
    const float* cw1    = (const float*)d_in[17];
    const float* cb1    = (const float*)d_in[18];
    const float* cw2    = (const float*)d_in[19];
    const float* cb2    = (const float*)d_in[20];
    const float* ln2_g  = (const float*)d_in[21];
    const float* ln2_b  = (const float*)d_in[22];
    const int*   rows   = (const int*)d_in[23];
    const int*   cols   = (const int*)d_in[24];
    float* out = (float*)d_out;

    int Nego = in_sizes[0] / 128;       // 100000
    int nnz  = in_sizes[1];             // 2000000
    int Mt   = in_sizes[6] / 128;       // 8192 = B*L
    int B    = Mt / LSEQ;               // 32
    int NL   = in_sizes[7] / (128 * 128);

    // ---- graph side ----
    zero_side_kernel<<<1024, 256>>>((Nego * 128) / 4);
    int nwarps = (nnz + EPW - 1) / EPW;
    int spmm_blocks = (nwarps * 32 + 255) / 256;
    spmm_kernel<<<spmm_blocks, 256>>>(ego, vals, rows, cols, nnz);
    agg_kernel<<<(Nego + 7) / 8, 128>>>(ego, W1, b1, W2, b2, out, Nego);

    // ---- transformer encoder ----
    const float* xin_ext = enc_in;
    int xin_id = -1;
    int gblocks = Mt / 8;   // 1024

    for (int i = 0; i < NL; i++) {
        const float* wq_ = wq + (size_t)i * D * D;  const float* bq_ = bq + i * D;
        const float* wk_ = wk + (size_t)i * D * D;  const float* bk_ = bk + i * D;
        const float* wv_ = wv + (size_t)i * D * D;  const float* bv_ = bv + i * D;
        const float* wo_ = wo + (size_t)i * D * D;  const float* bo_ = bo + i * D;
        const float* g1_ = ln1_g + i * D;           const float* be1_ = ln1_b + i * D;
        const float* c1_ = cw1 + (size_t)i * D * DI; const float* cb1_ = cb1 + i * DI;
        const float* c2_ = cw2 + (size_t)i * DI * D; const float* cb2_ = cb2 + i * D;
        const float* g2_ = ln2_g + i * D;           const float* be2_ = ln2_b + i * D;

        gemm_kernel<128, 128><<<gblocks, 128>>>(xin_ext, xin_id, wq_, bq_, nullptr, -1, nullptr, BQ, Mt, 0);
        gemm_kernel<128, 128><<<gblocks, 128>>>(xin_ext, xin_id, wk_, bk_, nullptr, -1, nullptr, BK, Mt, 0);
        gemm_kernel<128, 128><<<gblocks, 128>>>(xin_ext, xin_id, wv_, bv_, nullptr, -1, nullptr, BV, Mt, 0);
        attn_kernel<<<B * HEADS, 256>>>(0);
        gemm_kernel<128, 128><<<gblocks, 128>>>(nullptr, BO, wo_, bo_, xin_ext, xin_id, nullptr, BT, Mt, 2);
        ln_kernel<<<Mt, 128>>>(g1_, be1_, nullptr, BX1);
        gemm_kernel<128, 512><<<gblocks, 128>>>(nullptr, BX1, c1_, cb1_, nullptr, -1, nullptr, BH, Mt, 1);
        gemm_kernel<512, 128><<<gblocks, 128>>>(nullptr, BH, c2_, cb2_, nullptr, BX1, nullptr, BT, Mt, 2);
        bool last = (i == NL - 1);
        ln_kernel<<<Mt, 128>>>(g2_, be2_, last ? (out + (size_t)in_sizes[0]) : nullptr, BX2);
        xin_ext = nullptr;
        xin_id = BX2;
    }
}

// round 3
// speedup vs baseline: 1.2680x; 1.2680x over previous
#include <cuda_runtime.h>
#include <math.h>

#define DEV_INLINE __device__ __forceinline__

// Problem constants (shapes fixed by the dataset; N/NNZ/B read from in_sizes)
static const int D    = 128;
static const int LSEQ = 256;
static const int DK   = 16;
static const int DI   = 512;

// ------------------------- scratch (device globals) -------------------------
__device__ float g_side[12800000];   // side = A_in @ ego, then (ego+side)
__device__ float g_prod[12800000];   // ego * side
__device__ float g_q [1048576];
__device__ float g_k [1048576];
__device__ float g_v [1048576];
__device__ float g_o [1048576];
__device__ float g_t [1048576];
__device__ float g_x1[1048576];
__device__ float g_x2[1048576];
__device__ float g_h [4194304];      // 8192 x 512

enum { BQ = 0, BK = 1, BV = 2, BO = 3, BT = 4, BX1 = 5, BX2 = 6, BH = 7,
       BSIDE = 8, BPROD = 9 };

DEV_INLINE float* bufptr(int id) {
    switch (id) {
        case BQ:    return g_q;
        case BK:    return g_k;
        case BV:    return g_v;
        case BO:    return g_o;
        case BT:    return g_t;
        case BX1:   return g_x1;
        case BX2:   return g_x2;
        case BH:    return g_h;
        case BSIDE: return g_side;
        case BPROD: return g_prod;
    }
    return nullptr;
}

// ------------------------- f32x2 helpers -------------------------
DEV_INLINE unsigned long long pack2(float lo, float hi) {
    unsigned long long r;
    asm("mov.b64 %0, {%1, %2};" : "=l"(r) : "f"(lo), "f"(hi));
    return r;
}
DEV_INLINE void unpack2(unsigned long long v, float& lo, float& hi) {
    asm("mov.b64 {%0, %1}, %2;" : "=f"(lo), "=f"(hi) : "l"(v));
}
DEV_INLINE void ffma2(unsigned long long& d, unsigned long long a, unsigned long long b) {
    asm("fma.rn.f32x2 %0, %1, %2, %0;" : "+l"(d) : "l"(a), "l"(b));
}

// ------------------------------ zero side ------------------------------
__global__ void zero_side_kernel(int n4) {
    float4* p = reinterpret_cast<float4*>(g_side);
    int i = blockIdx.x * blockDim.x + threadIdx.x;
    int stride = gridDim.x * blockDim.x;
    float4 z = make_float4(0.f, 0.f, 0.f, 0.f);
    for (; i < n4; i += stride) p[i] = z;
}

// ------------------------------ SpMM (COO, rows sorted) ------------------------------
static const int EPW = 256;

DEV_INLINE void spmm_flush(int row, int lane, float4 acc) {
    float* p = &g_side[(size_t)row * 128 + lane * 4];
    atomicAdd(p + 0, acc.x);
    atomicAdd(p + 1, acc.y);
    atomicAdd(p + 2, acc.z);
    atomicAdd(p + 3, acc.w);
}

__global__ void __launch_bounds__(256) spmm_kernel(
    const float* __restrict__ ego, const float* __restrict__ vals,
    const int* __restrict__ rows, const int* __restrict__ cols, int nnz)
{
    int warp = (blockIdx.x * blockDim.x + threadIdx.x) >> 5;
    int lane = threadIdx.x & 31;
    long e0 = (long)warp * EPW;
    if (e0 >= nnz) return;
    long e1 = e0 + EPW; if (e1 > nnz) e1 = nnz;

    const float4* ego4 = reinterpret_cast<const float4*>(ego);
    float4 acc = make_float4(0.f, 0.f, 0.f, 0.f);
    int cur = rows[e0];
    for (long e = e0; e < e1; e++) {
        int r = rows[e];
        if (r != cur) {
            spmm_flush(cur, lane, acc);
            acc = make_float4(0.f, 0.f, 0.f, 0.f);
            cur = r;
        }
        float v  = vals[e];
        float4 g = ego4[(size_t)cols[e] * 32 + lane];
        acc.x += v * g.x; acc.y += v * g.y; acc.z += v * g.z; acc.w += v * g.w;
    }
    spmm_flush(cur, lane, acc);
}

// ------------------------------ prep: s = ego+side, p = ego*side ------------------------------
__global__ void __launch_bounds__(256) prep_kernel(const float* __restrict__ ego, int n4) {
    float4* s4 = reinterpret_cast<float4*>(g_side);
    float4* p4 = reinterpret_cast<float4*>(g_prod);
    const float4* e4 = reinterpret_cast<const float4*>(ego);
    int i = blockIdx.x * blockDim.x + threadIdx.x;
    int stride = gridDim.x * blockDim.x;
    for (; i < n4; i += stride) {
        float4 e = e4[i];
        float4 sd = s4[i];
        float4 s, p;
        s.x = e.x + sd.x; s.y = e.y + sd.y; s.z = e.z + sd.z; s.w = e.w + sd.w;
        p.x = e.x * sd.x; p.y = e.y * sd.y; p.z = e.z * sd.z; p.w = e.w * sd.w;
        s4[i] = s;
        p4[i] = p;
    }
}

// ------------------------------ tiled f32x2 GEMM core ------------------------------
// C[M,NOUT] = epilogue(A[M,K] @ W[K,NOUT] + bias)
// modes: 0 store, 1 relu, 2 add residual R, 3 leakyrelu store, 4 leakyrelu + add to existing C
// Tile: MT rows x 128 cols, 64-deep staged K chunks. Thread computes 8 rows x 4 cols,
// accumulated as 4x4 f32x2 (row pairs). A smem reads are warp-broadcast (no conflicts).
template<int K, int NOUT, int MT>
DEV_INLINE void gemm_core(const float* __restrict__ A, const float* __restrict__ W,
                          const float* __restrict__ bias, const float* __restrict__ R,
                          float* __restrict__ C, int M, int mode)
{
    constexpr int T = (MT / 8) * 32;
    __shared__ __align__(16) float Ws[64][128];
    __shared__ __align__(16) float As[64][MT];   // [k][r] transposed

    int tid  = threadIdx.x;
    int lane = tid & 31, wy = tid >> 5;
    int c0   = lane * 4;
    int r0   = wy * 8;
    int row0 = blockIdx.x * MT;
    int cb   = (NOUT > 128) ? (blockIdx.y * 128) : 0;

    unsigned long long acc[4][4];
    {
        float4 bv = *(const float4*)&bias[cb + c0];
        float bb[4] = {bv.x, bv.y, bv.z, bv.w};
        #pragma unroll
        for (int c = 0; c < 4; c++) {
            unsigned long long b2 = pack2(bb[c], bb[c]);
            #pragma unroll
            for (int p = 0; p < 4; p++) acc[p][c] = b2;
        }
    }

    for (int k0 = 0; k0 < K; k0 += 64) {
        // stage W chunk [64][128]
        #pragma unroll
        for (int i = 0; i < 2048 / T; i++) {
            int idx = tid + i * T;
            int k = idx >> 5, cg = idx & 31;
            *(float4*)&Ws[k][cg * 4] =
                *(const float4*)&W[(size_t)(k0 + k) * NOUT + cb + cg * 4];
        }
        // stage A chunk transposed: As[k][r]
        #pragma unroll
        for (int i = 0; i < (64 * MT / 4) / T; i++) {
            int idx = tid + i * T;
            int r = idx % MT, kg = idx / MT;
            int rr = row0 + r;
            float4 av = make_float4(0.f, 0.f, 0.f, 0.f);
            if (rr < M) av = *(const float4*)&A[(size_t)rr * K + k0 + kg * 4];
            As[kg * 4 + 0][r] = av.x;
            As[kg * 4 + 1][r] = av.y;
            As[kg * 4 + 2][r] = av.z;
            As[kg * 4 + 3][r] = av.w;
        }
        __syncthreads();

        #pragma unroll 4
        for (int k = 0; k < 64; k++) {
            float4 w4 = *(const float4*)&Ws[k][c0];
            unsigned long long wp[4];
            wp[0] = pack2(w4.x, w4.x);
            wp[1] = pack2(w4.y, w4.y);
            wp[2] = pack2(w4.z, w4.z);
            wp[3] = pack2(w4.w, w4.w);
            const unsigned long long* ap =
                reinterpret_cast<const unsigned long long*>(&As[k][r0]);
            unsigned long long a2[4] = {ap[0], ap[1], ap[2], ap[3]};
            #pragma unroll
            for (int p = 0; p < 4; p++)
                #pragma unroll
                for (int c = 0; c < 4; c++)
                    ffma2(acc[p][c], a2[p], wp[c]);
        }
        __syncthreads();
    }

    // epilogue
    #pragma unroll
    for (int p = 0; p < 4; p++) {
        float vv[2][4];
        #pragma unroll
        for (int c = 0; c < 4; c++) unpack2(acc[p][c], vv[0][c], vv[1][c]);
        #pragma unroll
        for (int h = 0; h < 2; h++) {
            int rr = row0 + r0 + 2 * p + h;
            if (rr >= M) continue;
            size_t off = (size_t)rr * NOUT + cb + c0;
            float x0 = vv[h][0], x1 = vv[h][1], x2 = vv[h][2], x3 = vv[h][3];
            if (mode == 1) {
                x0 = fmaxf(x0, 0.f); x1 = fmaxf(x1, 0.f);
                x2 = fmaxf(x2, 0.f); x3 = fmaxf(x3, 0.f);
            } else if (mode == 2) {
                float4 rv = *(const float4*)&R[off];
                x0 += rv.x; x1 += rv.y; x2 += rv.z; x3 += rv.w;
            } else if (mode == 3) {
                x0 = (x0 > 0.f) ? x0 : 0.01f * x0;
                x1 = (x1 > 0.f) ? x1 : 0.01f * x1;
                x2 = (x2 > 0.f) ? x2 : 0.01f * x2;
                x3 = (x3 > 0.f) ? x3 : 0.01f * x3;
            } else if (mode == 4) {
                x0 = (x0 > 0.f) ? x0 : 0.01f * x0;
                x1 = (x1 > 0.f) ? x1 : 0.01f * x1;
                x2 = (x2 > 0.f) ? x2 : 0.01f * x2;
                x3 = (x3 > 0.f) ? x3 : 0.01f * x3;
                float4 cv = *(const float4*)&C[off];
                x0 += cv.x; x1 += cv.y; x2 += cv.z; x3 += cv.w;
            }
            float4 o = make_float4(x0, x1, x2, x3);
            *(float4*)&C[off] = o;
        }
    }
}

template<int K, int NOUT, int MT>
__global__ void __launch_bounds__((MT / 8) * 32) gemm2_kernel(
    const float* __restrict__ Aext, int Aid,
    const float* __restrict__ W, const float* __restrict__ bias,
    const float* __restrict__ Rext, int Rid,
    float* __restrict__ Cext, int Cid, int M, int mode)
{
    const float* A = Aext ? Aext : bufptr(Aid);
    float*       C = Cext ? Cext : bufptr(Cid);
    const float* R = nullptr;
    if (mode == 2) R = Rext ? Rext : bufptr(Rid);
    gemm_core<K, NOUT, MT>(A, W, bias, R, C, M, mode);
}

// qkv fused: grid.y selects {q, k, v}
__global__ void __launch_bounds__(128) qkv_kernel(
    const float* __restrict__ Aext, int Aid,
    const float* __restrict__ wq, const float* __restrict__ bq,
    const float* __restrict__ wk, const float* __restrict__ bk,
    const float* __restrict__ wv, const float* __restrict__ bv, int M)
{
    int sel = blockIdx.y;
    const float* W = (sel == 0) ? wq : ((sel == 1) ? wk : wv);
    const float* b = (sel == 0) ? bq : ((sel == 1) ? bk : bv);
    const float* A = Aext ? Aext : bufptr(Aid);
    gemm_core<128, 128, 32>(A, W, b, nullptr, bufptr(BQ + sel), M, 0);
}

// ------------------------------ attention ------------------------------
__global__ void __launch_bounds__(256) attn_kernel(int unused)
{
    __shared__ __align__(16) float Ks[LSEQ * DK];
    __shared__ __align__(16) float Vs[LSEQ * DK];
    int b = blockIdx.x >> 3;
    int h = blockIdx.x & 7;
    int tid = threadIdx.x;           // query index l
    int base = (b * LSEQ) * D + h * DK;

    for (int idx = tid; idx < LSEQ * DK; idx += 256) {
        int m = idx >> 4, j = idx & 15;
        Ks[idx] = g_k[base + m * D + j];
        Vs[idx] = g_v[base + m * D + j];
    }
    __syncthreads();

    float q[16];
    {
        const float4* qp = reinterpret_cast<const float4*>(g_q + base + tid * D);
        #pragma unroll
        for (int jj = 0; jj < 4; jj++) {
            float4 t = qp[jj];
            q[jj * 4 + 0] = t.x; q[jj * 4 + 1] = t.y; q[jj * 4 + 2] = t.z; q[jj * 4 + 3] = t.w;
        }
    }

    float acc[16];
    #pragma unroll
    for (int j = 0; j < 16; j++) acc[j] = 0.f;
    float mx = -3.0e38f, sum = 0.f;

    const float4* Ks4 = reinterpret_cast<const float4*>(Ks);
    const float4* Vs4 = reinterpret_cast<const float4*>(Vs);

    for (int m = 0; m < LSEQ; m++) {
        float s = 0.f;
        #pragma unroll
        for (int jj = 0; jj < 4; jj++) {
            float4 kk = Ks4[m * 4 + jj];
            s += q[jj * 4 + 0] * kk.x + q[jj * 4 + 1] * kk.y
               + q[jj * 4 + 2] * kk.z + q[jj * 4 + 3] * kk.w;
        }
        s *= 0.25f;  // 1/sqrt(16)
        if (s <= mx) {
            // common path: max unchanged, no rescale
            float pe = __expf(s - mx);
            sum += pe;
            #pragma unroll
            for (int jj = 0; jj < 4; jj++) {
                float4 vv = Vs4[m * 4 + jj];
                acc[jj * 4 + 0] += pe * vv.x;
                acc[jj * 4 + 1] += pe * vv.y;
                acc[jj * 4 + 2] += pe * vv.z;
                acc[jj * 4 + 3] += pe * vv.w;
            }
        } else {
            float corr = __expf(mx - s);
            sum = sum * corr + 1.f;
            #pragma unroll
            for (int jj = 0; jj < 4; jj++) {
                float4 vv = Vs4[m * 4 + jj];
                acc[jj * 4 + 0] = acc[jj * 4 + 0] * corr + vv.x;
                acc[jj * 4 + 1] = acc[jj * 4 + 1] * corr + vv.y;
                acc[jj * 4 + 2] = acc[jj * 4 + 2] * corr + vv.z;
                acc[jj * 4 + 3] = acc[jj * 4 + 3] * corr + vv.w;
            }
            mx = s;
        }
    }

    float inv = 1.f / sum;
    float* op = g_o + base + tid * D;
    #pragma unroll
    for (int j = 0; j < 16; j++) op[j] = acc[j] * inv;
}

// ------------------------------ LayerNorm (reads g_t) ------------------------------
__global__ void __launch_bounds__(128) ln_kernel(
    const float* __restrict__ gamma, const float* __restrict__ beta,
    float* __restrict__ outext, int outid)
{
    float* out = outext ? outext : bufptr(outid);
    int row = blockIdx.x, tid = threadIdx.x;
    float v = g_t[(size_t)row * 128 + tid];

    float s = v, sq = v * v;
    #pragma unroll
    for (int o = 16; o > 0; o >>= 1) {
        s  += __shfl_xor_sync(0xffffffff, s,  o);
        sq += __shfl_xor_sync(0xffffffff, sq, o);
    }
    __shared__ float rs[4], rq[4];
    int w = tid >> 5, lane = tid & 31;
    if (lane == 0) { rs[w] = s; rq[w] = sq; }
    __syncthreads();
    float S = rs[0] + rs[1] + rs[2] + rs[3];
    float Q = rq[0] + rq[1] + rq[2] + rq[3];
    float m   = S * (1.f / 128.f);
    float var = Q * (1.f / 128.f) - m * m;
    float r   = rsqrtf(var + 1e-5f);
    out[(size_t)row * 128 + tid] = (v - m) * r * gamma[tid] + beta[tid];
}

// ------------------------------ launch ------------------------------
extern "C" void kernel_launch(void* const* d_in, const int* in_sizes, int n_in,
                              void* d_out, int out_size)
{
    const float* ego    = (const float*)d_in[0];
    const float* vals   = (const float*)d_in[1];
    const float* W1     = (const float*)d_in[2];
    const float* b1     = (const float*)d_in[3];
    const float* W2     = (const float*)d_in[4];
    const float* b2     = (const float*)d_in[5];
    const float* enc_in = (const float*)d_in[6];
    const float* wq     = (const float*)d_in[7];
    const float* bq     = (const float*)d_in[8];
    const float* wk     = (const float*)d_in[9];
    const float* bk     = (const float*)d_in[10];
    const float* wv     = (const float*)d_in[11];
    const float* bv     = (const float*)d_in[12];
    const float* wo     = (const float*)d_in[13];
    const float* bo     = (const float*)d_in[14];
    const float* ln1_g  = (const float*)d_in[15];
    const float* ln1_b  = (const float*)d_in[16];
    const float* cw1    = (const float*)d_in[17];
    const float* cb1    = (const float*)d_in[18];
    const float* cw2    = (const float*)d_in[19];
    const float* cb2    = (const float*)d_in[20];
    const float* ln2_g  = (const float*)d_in[21];
    const float* ln2_b  = (const float*)d_in[22];
    const int*   rows   = (const int*)d_in[23];
    const int*   cols   = (const int*)d_in[24];
    float* out = (float*)d_out;

    int Nego = in_sizes[0] / 128;       // 100000
    int nnz  = in_sizes[1];             // 2000000
    int Mt   = in_sizes[6] / 128;       // 8192 = B*L
    int B    = Mt / LSEQ;               // 32
    int NL   = in_sizes[7] / (128 * 128);

    // ---- graph side ----
    zero_side_kernel<<<1024, 256>>>((Nego * 128) / 4);
    int nwarps = (nnz + EPW - 1) / EPW;
    int spmm_blocks = (nwarps * 32 + 255) / 256;
    spmm_kernel<<<spmm_blocks, 256>>>(ego, vals, rows, cols, nnz);
    prep_kernel<<<1024, 256>>>(ego, (Nego * 128) / 4);

    int agg_blocks = (Nego + 63) / 64;
    gemm2_kernel<128, 128, 64><<<agg_blocks, 256>>>(nullptr, BSIDE, W1, b1, nullptr, -1, out, -1, Nego, 3);
    gemm2_kernel<128, 128, 64><<<agg_blocks, 256>>>(nullptr, BPROD, W2, b2, nullptr, -1, out, -1, Nego, 4);

    // ---- transformer encoder ----
    const float* xin_ext = enc_in;
    int xin_id = -1;
    int gblocks = Mt / 32;   // 256

    for (int i = 0; i < NL; i++) {
        const float* wq_ = wq + (size_t)i * D * D;  const float* bq_ = bq + i * D;
        const float* wk_ = wk + (size_t)i * D * D;  const float* bk_ = bk + i * D;
        const float* wv_ = wv + (size_t)i * D * D;  const float* bv_ = bv + i * D;
        const float* wo_ = wo + (size_t)i * D * D;  const float* bo_ = bo + i * D;
        const float* g1_ = ln1_g + i * D;            const float* be1_ = ln1_b + i * D;
        const float* c1_ = cw1 + (size_t)i * D * DI; const float* cb1_ = cb1 + i * DI;
        const float* c2_ = cw2 + (size_t)i * DI * D; const float* cb2_ = cb2 + i * D;
        const float* g2_ = ln2_g + i * D;            const float* be2_ = ln2_b + i * D;

        qkv_kernel<<<dim3(gblocks, 3), 128>>>(xin_ext, xin_id, wq_, bq_, wk_, bk_, wv_, bv_, Mt);
        attn_kernel<<<B * 8, 256>>>(0);
        gemm2_kernel<128, 128, 32><<<gblocks, 128>>>(nullptr, BO, wo_, bo_, xin_ext, xin_id, nullptr, BT, Mt, 2);
        ln_kernel<<<Mt, 128>>>(g1_, be1_, nullptr, BX1);
        gemm2_kernel<128, 512, 32><<<dim3(gblocks, 4), 128>>>(nullptr, BX1, c1_, cb1_, nullptr, -1, nullptr, BH, Mt, 1);
        gemm2_kernel<512, 128, 32><<<gblocks, 128>>>(nullptr, BH, c2_, cb2_, nullptr, BX1, nullptr, BT, Mt, 2);
        bool last = (i == NL - 1);
        ln_kernel<<<Mt, 128>>>(g2_, be2_, last ? (out + (size_t)in_sizes[0]) : nullptr, BX2);
        xin_ext = nullptr;
        xin_id = BX2;
    }
}

// round 4
// speedup vs baseline: 1.3939x; 1.0993x over previous
#include <cuda_runtime.h>
#include <math.h>

#define DEV_INLINE __device__ __forceinline__

static const int D    = 128;
static const int LSEQ = 256;
static const int DK   = 16;
static const int DI   = 512;

// ------------------------- scratch (device globals) -------------------------
__device__ float g_side[12800000];   // side = A_in @ ego
__device__ float g_q [1048576];
__device__ float g_k [1048576];
__device__ float g_v [1048576];
__device__ float g_o [1048576];
__device__ float g_x1[1048576];
__device__ float g_x2[1048576];
__device__ float g_h [4194304];      // 8192 x 512

enum { BQ = 0, BK = 1, BV = 2, BO = 3, BX1 = 5, BX2 = 6, BH = 7 };

DEV_INLINE float* bufptr(int id) {
    switch (id) {
        case BQ:    return g_q;
        case BK:    return g_k;
        case BV:    return g_v;
        case BO:    return g_o;
        case BX1:   return g_x1;
        case BX2:   return g_x2;
        case BH:    return g_h;
    }
    return nullptr;
}

// ------------------------- f32x2 helpers -------------------------
DEV_INLINE unsigned long long pack2(float lo, float hi) {
    unsigned long long r;
    asm("mov.b64 %0, {%1, %2};" : "=l"(r) : "f"(lo), "f"(hi));
    return r;
}
DEV_INLINE void unpack2(unsigned long long v, float& lo, float& hi) {
    asm("mov.b64 {%0, %1}, %2;" : "=f"(lo), "=f"(hi) : "l"(v));
}
DEV_INLINE void ffma2(unsigned long long& d, unsigned long long a, unsigned long long b) {
    asm("fma.rn.f32x2 %0, %1, %2, %0;" : "+l"(d) : "l"(a), "l"(b));
}

// ------------------------------ zero side ------------------------------
__global__ void zero_side_kernel(int n4) {
    float4* p = reinterpret_cast<float4*>(g_side);
    int i = blockIdx.x * blockDim.x + threadIdx.x;
    int stride = gridDim.x * blockDim.x;
    float4 z = make_float4(0.f, 0.f, 0.f, 0.f);
    for (; i < n4; i += stride) p[i] = z;
}

// ------------------------------ SpMM (COO, rows sorted) ------------------------------
static const int EPW = 256;

DEV_INLINE void spmm_flush(int row, int lane, float4 acc) {
    float* p = &g_side[(size_t)row * 128 + lane * 4];
    atomicAdd(p + 0, acc.x);
    atomicAdd(p + 1, acc.y);
    atomicAdd(p + 2, acc.z);
    atomicAdd(p + 3, acc.w);
}

__global__ void __launch_bounds__(256) spmm_kernel(
    const float* __restrict__ ego, const float* __restrict__ vals,
    const int* __restrict__ rows, const int* __restrict__ cols, int nnz)
{
    int warp = (blockIdx.x * blockDim.x + threadIdx.x) >> 5;
    int lane = threadIdx.x & 31;
    long e0 = (long)warp * EPW;
    if (e0 >= nnz) return;
    long e1 = e0 + EPW; if (e1 > nnz) e1 = nnz;

    const float4* ego4 = reinterpret_cast<const float4*>(ego);
    float4 acc = make_float4(0.f, 0.f, 0.f, 0.f);
    int cur = rows[e0];
    for (long e = e0; e < e1; e++) {
        int r = rows[e];
        if (r != cur) {
            spmm_flush(cur, lane, acc);
            acc = make_float4(0.f, 0.f, 0.f, 0.f);
            cur = r;
        }
        float v  = vals[e];
        float4 g = ego4[(size_t)cols[e] * 32 + lane];
        acc.x += v * g.x; acc.y += v * g.y; acc.z += v * g.z; acc.w += v * g.w;
    }
    spmm_flush(cur, lane, acc);
}

// ------------------------------ fused aggregator ------------------------------
// out = leaky((ego+side)@W1+b1) + leaky((ego*side)@W2+b2), one pass.
// Block: 256 thr, tile 64 rows x 128 cols, K chunks of 32.
__global__ void __launch_bounds__(256) agg_fused_kernel(
    const float* __restrict__ ego,
    const float* __restrict__ W1, const float* __restrict__ b1,
    const float* __restrict__ W2, const float* __restrict__ b2,
    float* __restrict__ out, int M)
{
    __shared__ __align__(16) float W1s[32][128];
    __shared__ __align__(16) float W2s[32][128];
    __shared__ __align__(16) float As[32][64];   // (ego+side) transposed [k][r]
    __shared__ __align__(16) float Ps[32][64];   // (ego*side) transposed

    int tid  = threadIdx.x;
    int lane = tid & 31, wy = tid >> 5;
    int c0   = lane * 4;
    int r0   = wy * 8;
    int row0 = blockIdx.x * 64;

    unsigned long long acc1[4][4], acc2[4][4];
    {
        float4 bv1 = *(const float4*)&b1[c0];
        float4 bv2 = *(const float4*)&b2[c0];
        float a1[4] = {bv1.x, bv1.y, bv1.z, bv1.w};
        float a2[4] = {bv2.x, bv2.y, bv2.z, bv2.w};
        #pragma unroll
        for (int c = 0; c < 4; c++) {
            unsigned long long p1 = pack2(a1[c], a1[c]);
            unsigned long long p2 = pack2(a2[c], a2[c]);
            #pragma unroll
            for (int p = 0; p < 4; p++) { acc1[p][c] = p1; acc2[p][c] = p2; }
        }
    }

    for (int k0 = 0; k0 < 128; k0 += 32) {
        // stage W1/W2 chunk [32][128]
        #pragma unroll
        for (int i = 0; i < 4; i++) {
            int idx = tid + i * 256;
            int k = idx >> 5, cg = idx & 31;
            *(float4*)&W1s[k][cg * 4] = *(const float4*)&W1[(size_t)(k0 + k) * 128 + cg * 4];
            *(float4*)&W2s[k][cg * 4] = *(const float4*)&W2[(size_t)(k0 + k) * 128 + cg * 4];
        }
        // stage A chunks transposed, computing s = e+sd, p = e*sd on the fly
        #pragma unroll
        for (int i = 0; i < 2; i++) {
            int idx = tid + i * 256;
            int r = idx & 63, kg = idx >> 6;
            int rr = row0 + r;
            float4 e = make_float4(0.f, 0.f, 0.f, 0.f);
            float4 sd = make_float4(0.f, 0.f, 0.f, 0.f);
            if (rr < M) {
                e  = *(const float4*)&ego   [(size_t)rr * 128 + k0 + kg * 4];
                sd = *(const float4*)&g_side[(size_t)rr * 128 + k0 + kg * 4];
            }
            As[kg * 4 + 0][r] = e.x + sd.x;
            As[kg * 4 + 1][r] = e.y + sd.y;
            As[kg * 4 + 2][r] = e.z + sd.z;
            As[kg * 4 + 3][r] = e.w + sd.w;
            Ps[kg * 4 + 0][r] = e.x * sd.x;
            Ps[kg * 4 + 1][r] = e.y * sd.y;
            Ps[kg * 4 + 2][r] = e.z * sd.z;
            Ps[kg * 4 + 3][r] = e.w * sd.w;
        }
        __syncthreads();

        #pragma unroll 4
        for (int k = 0; k < 32; k++) {
            float4 w14 = *(const float4*)&W1s[k][c0];
            float4 w24 = *(const float4*)&W2s[k][c0];
            unsigned long long wp1[4], wp2[4];
            wp1[0] = pack2(w14.x, w14.x); wp1[1] = pack2(w14.y, w14.y);
            wp1[2] = pack2(w14.z, w14.z); wp1[3] = pack2(w14.w, w14.w);
            wp2[0] = pack2(w24.x, w24.x); wp2[1] = pack2(w24.y, w24.y);
            wp2[2] = pack2(w24.z, w24.z); wp2[3] = pack2(w24.w, w24.w);
            const unsigned long long* as2 = reinterpret_cast<const unsigned long long*>(&As[k][r0]);
            const unsigned long long* ps2 = reinterpret_cast<const unsigned long long*>(&Ps[k][r0]);
            unsigned long long a_s[4] = {as2[0], as2[1], as2[2], as2[3]};
            unsigned long long a_p[4] = {ps2[0], ps2[1], ps2[2], ps2[3]};
            #pragma unroll
            for (int p = 0; p < 4; p++) {
                #pragma unroll
                for (int c = 0; c < 4; c++) {
                    ffma2(acc1[p][c], a_s[p], wp1[c]);
                    ffma2(acc2[p][c], a_p[p], wp2[c]);
                }
            }
        }
        __syncthreads();
    }

    // epilogue: leaky(acc1) + leaky(acc2), single store
    #pragma unroll
    for (int p = 0; p < 4; p++) {
        float v1[2][4], v2[2][4];
        #pragma unroll
        for (int c = 0; c < 4; c++) {
            unpack2(acc1[p][c], v1[0][c], v1[1][c]);
            unpack2(acc2[p][c], v2[0][c], v2[1][c]);
        }
        #pragma unroll
        for (int h = 0; h < 2; h++) {
            int rr = row0 + r0 + 2 * p + h;
            if (rr >= M) continue;
            float o[4];
            #pragma unroll
            for (int c = 0; c < 4; c++) {
                float x = v1[h][c]; x = (x > 0.f) ? x : 0.01f * x;
                float y = v2[h][c]; y = (y > 0.f) ? y : 0.01f * y;
                o[c] = x + y;
            }
            *(float4*)&out[(size_t)rr * 128 + c0] =
                make_float4(o[0], o[1], o[2], o[3]);
        }
    }
}

// ------------------------------ tiled f32x2 GEMM core ------------------------------
// modes: 0 store, 1 relu, 2 add residual R, 5 add residual R then LayerNorm(gamma,beta)
template<int K, int NOUT, int MT>
DEV_INLINE void gemm_core(const float* __restrict__ A, const float* __restrict__ W,
                          const float* __restrict__ bias, const float* __restrict__ R,
                          const float* __restrict__ lnG, const float* __restrict__ lnB,
                          float* __restrict__ C, int M, int mode)
{
    constexpr int T = (MT / 8) * 32;
    __shared__ __align__(16) float Ws[64][128];
    __shared__ __align__(16) float As[64][MT];   // [k][r] transposed

    int tid  = threadIdx.x;
    int lane = tid & 31, wy = tid >> 5;
    int c0   = lane * 4;
    int r0   = wy * 8;
    int row0 = blockIdx.x * MT;
    int cb   = (NOUT > 128) ? (blockIdx.y * 128) : 0;

    unsigned long long acc[4][4];
    {
        float4 bv = *(const float4*)&bias[cb + c0];
        float bb[4] = {bv.x, bv.y, bv.z, bv.w};
        #pragma unroll
        for (int c = 0; c < 4; c++) {
            unsigned long long b2 = pack2(bb[c], bb[c]);
            #pragma unroll
            for (int p = 0; p < 4; p++) acc[p][c] = b2;
        }
    }

    for (int k0 = 0; k0 < K; k0 += 64) {
        #pragma unroll
        for (int i = 0; i < 2048 / T; i++) {
            int idx = tid + i * T;
            int k = idx >> 5, cg = idx & 31;
            *(float4*)&Ws[k][cg * 4] =
                *(const float4*)&W[(size_t)(k0 + k) * NOUT + cb + cg * 4];
        }
        #pragma unroll
        for (int i = 0; i < (64 * MT / 4) / T; i++) {
            int idx = tid + i * T;
            int r = idx % MT, kg = idx / MT;
            int rr = row0 + r;
            float4 av = make_float4(0.f, 0.f, 0.f, 0.f);
            if (rr < M) av = *(const float4*)&A[(size_t)rr * K + k0 + kg * 4];
            As[kg * 4 + 0][r] = av.x;
            As[kg * 4 + 1][r] = av.y;
            As[kg * 4 + 2][r] = av.z;
            As[kg * 4 + 3][r] = av.w;
        }
        __syncthreads();

        #pragma unroll 4
        for (int k = 0; k < 64; k++) {
            float4 w4 = *(const float4*)&Ws[k][c0];
            unsigned long long wp[4];
            wp[0] = pack2(w4.x, w4.x);
            wp[1] = pack2(w4.y, w4.y);
            wp[2] = pack2(w4.z, w4.z);
            wp[3] = pack2(w4.w, w4.w);
            const unsigned long long* ap =
                reinterpret_cast<const unsigned long long*>(&As[k][r0]);
            unsigned long long a2[4] = {ap[0], ap[1], ap[2], ap[3]};
            #pragma unroll
            for (int p = 0; p < 4; p++)
                #pragma unroll
                for (int c = 0; c < 4; c++)
                    ffma2(acc[p][c], a2[p], wp[c]);
        }
        __syncthreads();
    }

    float4 g4 = make_float4(1.f, 1.f, 1.f, 1.f);
    float4 be4 = make_float4(0.f, 0.f, 0.f, 0.f);
    if (mode == 5) {
        g4  = *(const float4*)&lnG[c0];
        be4 = *(const float4*)&lnB[c0];
    }

    #pragma unroll
    for (int p = 0; p < 4; p++) {
        float vv[2][4];
        #pragma unroll
        for (int c = 0; c < 4; c++) unpack2(acc[p][c], vv[0][c], vv[1][c]);
        #pragma unroll
        for (int h = 0; h < 2; h++) {
            int rr = row0 + r0 + 2 * p + h;   // warp-uniform
            if (rr >= M) continue;
            size_t off = (size_t)rr * NOUT + cb + c0;
            float x0 = vv[h][0], x1 = vv[h][1], x2 = vv[h][2], x3 = vv[h][3];
            if (mode == 1) {
                x0 = fmaxf(x0, 0.f); x1 = fmaxf(x1, 0.f);
                x2 = fmaxf(x2, 0.f); x3 = fmaxf(x3, 0.f);
            } else if (mode == 2) {
                float4 rv = *(const float4*)&R[off];
                x0 += rv.x; x1 += rv.y; x2 += rv.z; x3 += rv.w;
            } else if (mode == 5) {
                float4 rv = *(const float4*)&R[off];
                x0 += rv.x; x1 += rv.y; x2 += rv.z; x3 += rv.w;
                // LayerNorm over the row (128 cols spread over 32 lanes x 4)
                float s  = x0 + x1 + x2 + x3;
                float sq = x0 * x0 + x1 * x1 + x2 * x2 + x3 * x3;
                #pragma unroll
                for (int o = 16; o > 0; o >>= 1) {
                    s  += __shfl_xor_sync(0xffffffff, s,  o);
                    sq += __shfl_xor_sync(0xffffffff, sq, o);
                }
                float m   = s * (1.f / 128.f);
                float var = sq * (1.f / 128.f) - m * m;
                float rstd = rsqrtf(var + 1e-5f);
                x0 = (x0 - m) * rstd * g4.x + be4.x;
                x1 = (x1 - m) * rstd * g4.y + be4.y;
                x2 = (x2 - m) * rstd * g4.z + be4.z;
                x3 = (x3 - m) * rstd * g4.w + be4.w;
            }
            *(float4*)&C[off] = make_float4(x0, x1, x2, x3);
        }
    }
}

template<int K, int NOUT, int MT>
__global__ void __launch_bounds__((MT / 8) * 32) gemm2_kernel(
    const float* __restrict__ Aext, int Aid,
    const float* __restrict__ W, const float* __restrict__ bias,
    const float* __restrict__ Rext, int Rid,
    const float* __restrict__ lnG, const float* __restrict__ lnB,
    float* __restrict__ Cext, int Cid, int M, int mode)
{
    const float* A = Aext ? Aext : bufptr(Aid);
    float*       C = Cext ? Cext : bufptr(Cid);
    const float* R = nullptr;
    if (mode == 2 || mode == 5) R = Rext ? Rext : bufptr(Rid);
    gemm_core<K, NOUT, MT>(A, W, bias, R, lnG, lnB, C, M, mode);
}

// qkv fused: grid.y selects {q, k, v}
__global__ void __launch_bounds__(128) qkv_kernel(
    const float* __restrict__ Aext, int Aid,
    const float* __restrict__ wq, const float* __restrict__ bq,
    const float* __restrict__ wk, const float* __restrict__ bk,
    const float* __restrict__ wv, const float* __restrict__ bv, int M)
{
    int sel = blockIdx.y;
    const float* W = (sel == 0) ? wq : ((sel == 1) ? wk : wv);
    const float* b = (sel == 0) ? bq : ((sel == 1) ? bk : bv);
    const float* A = Aext ? Aext : bufptr(Aid);
    gemm_core<128, 128, 32>(A, W, b, nullptr, nullptr, nullptr, bufptr(BQ + sel), M, 0);
}

// ------------------------------ attention ------------------------------
__global__ void __launch_bounds__(256) attn_kernel(int unused)
{
    __shared__ __align__(16) float Ks[LSEQ * DK];
    __shared__ __align__(16) float Vs[LSEQ * DK];
    int b = blockIdx.x >> 3;
    int h = blockIdx.x & 7;
    int tid = threadIdx.x;           // query index l
    int base = (b * LSEQ) * D + h * DK;

    for (int idx = tid; idx < LSEQ * DK; idx += 256) {
        int m = idx >> 4, j = idx & 15;
        Ks[idx] = g_k[base + m * D + j];
        Vs[idx] = g_v[base + m * D + j];
    }
    __syncthreads();

    float q[16];
    {
        const float4* qp = reinterpret_cast<const float4*>(g_q + base + tid * D);
        #pragma unroll
        for (int jj = 0; jj < 4; jj++) {
            float4 t = qp[jj];
            q[jj * 4 + 0] = t.x; q[jj * 4 + 1] = t.y; q[jj * 4 + 2] = t.z; q[jj * 4 + 3] = t.w;
        }
    }

    float acc[16];
    #pragma unroll
    for (int j = 0; j < 16; j++) acc[j] = 0.f;
    float mx = -3.0e38f, sum = 0.f;

    const float4* Ks4 = reinterpret_cast<const float4*>(Ks);
    const float4* Vs4 = reinterpret_cast<const float4*>(Vs);

    for (int m = 0; m < LSEQ; m++) {
        float s = 0.f;
        #pragma unroll
        for (int jj = 0; jj < 4; jj++) {
            float4 kk = Ks4[m * 4 + jj];
            s += q[jj * 4 + 0] * kk.x + q[jj * 4 + 1] * kk.y
               + q[jj * 4 + 2] * kk.z + q[jj * 4 + 3] * kk.w;
        }
        s *= 0.25f;  // 1/sqrt(16)
        if (s <= mx) {
            float pe = __expf(s - mx);
            sum += pe;
            #pragma unroll
            for (int jj = 0; jj < 4; jj++) {
                float4 vv = Vs4[m * 4 + jj];
                acc[jj * 4 + 0] += pe * vv.x;
                acc[jj * 4 + 1] += pe * vv.y;
                acc[jj * 4 + 2] += pe * vv.z;
                acc[jj * 4 + 3] += pe * vv.w;
            }
        } else {
            float corr = __expf(mx - s);
            sum = sum * corr + 1.f;
            #pragma unroll
            for (int jj = 0; jj < 4; jj++) {
                float4 vv = Vs4[m * 4 + jj];
                acc[jj * 4 + 0] = acc[jj * 4 + 0] * corr + vv.x;
                acc[jj * 4 + 1] = acc[jj * 4 + 1] * corr + vv.y;
                acc[jj * 4 + 2] = acc[jj * 4 + 2] * corr + vv.z;
                acc[jj * 4 + 3] = acc[jj * 4 + 3] * corr + vv.w;
            }
            mx = s;
        }
    }

    float inv = 1.f / sum;
    float* op = g_o + base + tid * D;
    #pragma unroll
    for (int j = 0; j < 16; j++) op[j] = acc[j] * inv;
}

// ------------------------------ launch ------------------------------
extern "C" void kernel_launch(void* const* d_in, const int* in_sizes, int n_in,
                              void* d_out, int out_size)
{
    const float* ego    = (const float*)d_in[0];
    const float* vals   = (const float*)d_in[1];
    const float* W1     = (const float*)d_in[2];
    const float* b1     = (const float*)d_in[3];
    const float* W2     = (const float*)d_in[4];
    const float* b2     = (const float*)d_in[5];
    const float* enc_in = (const float*)d_in[6];
    const float* wq     = (const float*)d_in[7];
    const float* bq     = (const float*)d_in[8];
    const float* wk     = (const float*)d_in[9];
    const float* bk     = (const float*)d_in[10];
    const float* wv     = (const float*)d_in[11];
    const float* bv     = (const float*)d_in[12];
    const float* wo     = (const float*)d_in[13];
    const float* bo     = (const float*)d_in[14];
    const float* ln1_g  = (const float*)d_in[15];
    const float* ln1_b  = (const float*)d_in[16];
    const float* cw1    = (const float*)d_in[17];
    const float* cb1    = (const float*)d_in[18];
    const float* cw2    = (const float*)d_in[19];
    const float* cb2    = (const float*)d_in[20];
    const float* ln2_g  = (const float*)d_in[21];
    const float* ln2_b  = (const float*)d_in[22];
    const int*   rows   = (const int*)d_in[23];
    const int*   cols   = (const int*)d_in[24];
    float* out = (float*)d_out;

    int Nego = in_sizes[0] / 128;       // 100000
    int nnz  = in_sizes[1];             // 2000000
    int Mt   = in_sizes[6] / 128;       // 8192 = B*L
    int B    = Mt / LSEQ;               // 32
    int NL   = in_sizes[7] / (128 * 128);

    // ---- graph side ----
    zero_side_kernel<<<1024, 256>>>((Nego * 128) / 4);
    int nwarps = (nnz + EPW - 1) / EPW;
    int spmm_blocks = (nwarps * 32 + 255) / 256;
    spmm_kernel<<<spmm_blocks, 256>>>(ego, vals, rows, cols, nnz);
    agg_fused_kernel<<<(Nego + 63) / 64, 256>>>(ego, W1, b1, W2, b2, out, Nego);

    // ---- transformer encoder ----
    const float* xin_ext = enc_in;
    int xin_id = -1;
    int gblocks = Mt / 32;   // 256

    for (int i = 0; i < NL; i++) {
        const float* wq_ = wq + (size_t)i * D * D;  const float* bq_ = bq + i * D;
        const float* wk_ = wk + (size_t)i * D * D;  const float* bk_ = bk + i * D;
        const float* wv_ = wv + (size_t)i * D * D;  const float* bv_ = bv + i * D;
        const float* wo_ = wo + (size_t)i * D * D;  const float* bo_ = bo + i * D;
        const float* g1_ = ln1_g + i * D;            const float* be1_ = ln1_b + i * D;
        const float* c1_ = cw1 + (size_t)i * D * DI; const float* cb1_ = cb1 + i * DI;
        const float* c2_ = cw2 + (size_t)i * DI * D; const float* cb2_ = cb2 + i * D;
        const float* g2_ = ln2_g + i * D;            const float* be2_ = ln2_b + i * D;

        qkv_kernel<<<dim3(gblocks, 3), 128>>>(xin_ext, xin_id, wq_, bq_, wk_, bk_, wv_, bv_, Mt);
        attn_kernel<<<B * 8, 256>>>(0);
        // wo GEMM + residual + LN1 fused -> BX1
        gemm2_kernel<128, 128, 32><<<gblocks, 128>>>(nullptr, BO, wo_, bo_, xin_ext, xin_id,
                                                     g1_, be1_, nullptr, BX1, Mt, 5);
        // FFN1 (relu) -> BH
        gemm2_kernel<128, 512, 32><<<dim3(gblocks, 4), 128>>>(nullptr, BX1, c1_, cb1_, nullptr, -1,
                                                              nullptr, nullptr, nullptr, BH, Mt, 1);
        // FFN2 + residual(BX1) + LN2 fused -> BX2 (or final output region)
        bool last = (i == NL - 1);
        gemm2_kernel<512, 128, 32><<<gblocks, 128>>>(nullptr, BH, c2_, cb2_, nullptr, BX1,
                                                     g2_, be2_,
                                                     last ? (out + (size_t)in_sizes[0]) : nullptr,
                                                     BX2, Mt, 5);
        xin_ext = nullptr;
        xin_id = BX2;
    }
}